// round 1
// baseline (speedup 1.0000x reference)
#include <cuda_runtime.h>
#include <math.h>

// Problem constants
#define NPIX   65536        // B*H*W = 16*64*64
#define HW     4096         // 64*64
#define TILE   128          // pixels per block
#define NBLK   (NPIX/TILE)  // 512
#define NTHR   256          // threads per block (TILE pixels * 2 groups)

// Output layout (flattened tuple, float32):
// zq[16,18,64,64] | loss | cb_entropy | indices[16,64,64] | group_indices[16,64,64,2] | avg_prob[2,512]
#define OFF_ZQ    0
#define OFF_LOSS  1179648
#define OFF_CBE   1179649
#define OFF_IDX   1179650
#define OFF_GIDX  1245186
#define OFF_AVGP  1376258

// Deterministic per-block partials (no float atomics -> bitwise reproducible)
__device__ float g_pavg[NBLK * 1024];
__device__ float g_pcommit[NBLK];
__device__ float g_pent[NBLK];

__global__ void __launch_bounds__(NTHR) bsq_main(const float* __restrict__ z,
                                                 float* __restrict__ out) {
    extern __shared__ float sBuf[];          // TILE*96 floats (hi16+lo32 per pixel per group) + 64 reduction
    float* sRed = sBuf + TILE * 96;

    const int t   = threadIdx.x;
    const int blk = blockIdx.x;
    const int pix = t >> 1;                  // 0..127
    const int g   = t & 1;                   // group 0/1
    const int P   = blk * TILE + pix;        // global pixel
    const int b   = P >> 12;                 // batch
    const int hw  = P & 4095;

    const float* zp  = z   + (size_t)(b * 18 + g * 9) * HW + hw;
    float*       zqp = out + OFF_ZQ + (size_t)(b * 18 + g * 9) * HW + hw;

    // ---- Phase 1: per-(pixel,group) work ----
    float p[9];
    unsigned gidx = 0;
    float commit = 0.f, ent = 0.f;
#pragma unroll
    for (int j = 0; j < 9; j++) {
        float v = zp[j * HW];
        bool s = v > 0.f;
        gidx = (gidx << 1) | (unsigned)s;
        float zh = s ? 1.f : -1.f;
        zqp[j * HW] = zh;                    // zq forward value == sign(z)
        float d = zh - v;
        commit += d * d;
        // p_j = P(bit=+1) = sigmoid(4 z)
        p[j] = 1.f / (1.f + __expf(-4.f * v));
        // binary entropy, numerically stable via the small-side prob q = sigmoid(-4|z|)
        float a = 4.f * fabsf(v);
        float q = 1.f / (1.f + __expf(a));
        ent += -q * __logf(q) - (1.f - q) * log1pf(-q);
    }

    // indices: pair of threads (g=0,g=1) are adjacent lanes
    unsigned other = __shfl_xor_sync(0xffffffffu, gidx, 1);
    out[OFF_GIDX + (size_t)P * 2 + g] = (float)gidx;
    if (g == 0)
        out[OFF_IDX + P] = (float)(gidx * 512u + other);

    // hi/lo product tables: prob[d] = hi[d>>5] * lo[d&31]
    float* sp = sBuf + pix * 96 + g * 48;
    {
        float hi[16];
        hi[0] = 1.f - p[0]; hi[1] = p[0];
#pragma unroll
        for (int c = 1; c < 4; c++) {
            const int n = 1 << c;
#pragma unroll
            for (int i = n - 1; i >= 0; i--) {
                float v = hi[i];
                hi[2 * i + 1] = v * p[c];
                hi[2 * i]     = v * (1.f - p[c]);
            }
        }
#pragma unroll
        for (int i = 0; i < 16; i++) sp[i] = hi[i];
    }
    {
        float lo[32];
        lo[0] = 1.f - p[4]; lo[1] = p[4];
#pragma unroll
        for (int c = 1; c < 5; c++) {
            const int n = 1 << c;
#pragma unroll
            for (int i = n - 1; i >= 0; i--) {
                float v = lo[i];
                lo[2 * i + 1] = v * p[4 + c];
                lo[2 * i]     = v * (1.f - p[4 + c]);
            }
        }
#pragma unroll
        for (int i = 0; i < 32; i++) sp[16 + i] = lo[i];
    }

    // block-reduce commit & entropy (deterministic shuffle tree)
#pragma unroll
    for (int o = 16; o; o >>= 1) {
        commit += __shfl_down_sync(0xffffffffu, commit, o);
        ent    += __shfl_down_sync(0xffffffffu, ent, o);
    }
    const int wid = t >> 5, lid = t & 31;
    if (lid == 0) { sRed[wid] = commit; sRed[8 + wid] = ent; }

    __syncthreads();   // sBuf ready for phase 2, sRed ready for thread 0

    if (t == 0) {
        float c = 0.f, e = 0.f;
#pragma unroll
        for (int w = 0; w < 8; w++) { c += sRed[w]; e += sRed[8 + w]; }
        g_pcommit[blk] = c;
        g_pent[blk]    = e;
    }

    // ---- Phase 2: avg_prob partials. Thread owns 4 consecutive codebook slots ----
    const int slot  = 4 * t;              // 0..1023, slot = g*512 + d
    const int gg    = slot >> 9;
    const int dbase = slot & 511;
    const int hiI   = dbase >> 5;         // same for all 4 slots (4-aligned)
    const int loI   = dbase & 31;
    float4 acc = make_float4(0.f, 0.f, 0.f, 0.f);
    const float* base = sBuf + gg * 48;
#pragma unroll 4
    for (int px = 0; px < TILE; px++) {
        const float* bp = base + px * 96;
        float  h = bp[hiI];                               // broadcast LDS
        float4 l = *(const float4*)(bp + 16 + loI);       // LDS.128
        acc.x += h * l.x; acc.y += h * l.y;
        acc.z += h * l.z; acc.w += h * l.w;
    }
    *(float4*)(g_pavg + (size_t)blk * 1024 + slot) = acc;
}

__global__ void __launch_bounds__(1024) bsq_final(float* __restrict__ out) {
    __shared__ float sr[64];
    const int t = threadIdx.x;            // 1024 threads, one per (g,d) slot
    const int wid = t >> 5, lid = t & 31;

    // avg_prob: deterministic serial sum over 512 block-partials (coalesced)
    float s = 0.f;
    for (int b = 0; b < NBLK; b++) s += g_pavg[(size_t)b * 1024 + t];
    float avg = s * (1.f / (float)NPIX);
    out[OFF_AVGP + t] = avg;

    float cterm = -avg * __logf(avg + 1e-8f);
#pragma unroll
    for (int o = 16; o; o >>= 1) cterm += __shfl_down_sync(0xffffffffu, cterm, o);
    if (lid == 0) sr[wid] = cterm;        // warps 0..31

    // commit / entropy partials: threads 0..511 (warps 0..15)
    float cm = (t < NBLK) ? g_pcommit[t] : 0.f;
    float en = (t < NBLK) ? g_pent[t]    : 0.f;
#pragma unroll
    for (int o = 16; o; o >>= 1) {
        cm += __shfl_down_sync(0xffffffffu, cm, o);
        en += __shfl_down_sync(0xffffffffu, en, o);
    }
    __syncthreads();                      // sr[0..31] written
    if (lid == 0 && wid < 16) { sr[32 + wid] = cm; sr[48 + wid] = en; }
    __syncthreads();

    if (t == 0) {
        float cbE = 0.f, cmS = 0.f, enS = 0.f;
#pragma unroll
        for (int w = 0; w < 32; w++) cbE += sr[w];
#pragma unroll
        for (int w = 0; w < 16; w++) { cmS += sr[32 + w]; enS += sr[48 + w]; }
        float commit_loss = 0.25f * cmS * (1.f / (float)NPIX);   // BETA * mean(sum_c d^2)
        float pse = enS * (1.f / (float)NPIX);                   // per-sample entropy
        float loss = commit_loss + pse - cbE;                    // GAMMA0=GAMMA=ZETA=INV_T=1
        out[OFF_LOSS] = loss;
        out[OFF_CBE]  = cbE;
    }
}

extern "C" void kernel_launch(void* const* d_in, const int* in_sizes, int n_in,
                              void* d_out, int out_size) {
    const float* z = (const float*)d_in[0];
    float* out = (float*)d_out;

    const size_t smem = (TILE * 96 + 64) * sizeof(float);   // 49,408 B
    cudaFuncSetAttribute(bsq_main, cudaFuncAttributeMaxDynamicSharedMemorySize, 64 * 1024);

    bsq_main<<<NBLK, NTHR, smem>>>(z, out);
    bsq_final<<<1, 1024>>>(out);
}

// round 2
// speedup vs baseline: 1.5007x; 1.5007x over previous
#include <cuda_runtime.h>
#include <math.h>

// Problem constants
#define NPIX   65536        // B*H*W = 16*64*64
#define HW     4096         // 64*64
#define TILE   128          // pixels per block
#define NBLK   (NPIX/TILE)  // 512
#define NTHR   256
#define NSPLIT 8            // reduction splits (512 blocks -> 8 partials)

// Output layout (flattened tuple, float32):
// zq[16,18,64,64] | loss | cb_entropy | indices[16,64,64] | group_indices[16,64,64,2] | avg_prob[2,512]
#define OFF_ZQ    0
#define OFF_LOSS  1179648
#define OFF_CBE   1179649
#define OFF_IDX   1179650
#define OFF_GIDX  1245186
#define OFF_AVGP  1376258

// Deterministic per-block partials (no float atomics -> bitwise reproducible)
__device__ float g_pavg[NBLK * 1024];
__device__ float g_red[NSPLIT * 1024];
__device__ float g_pcommit[NBLK];
__device__ float g_pent[NBLK];

__global__ void __launch_bounds__(NTHR) bsq_main(const float* __restrict__ z,
                                                 float* __restrict__ out) {
    extern __shared__ float sBuf[];          // TILE*96 table floats + 64 reduction
    float* sRed = sBuf + TILE * 96;

    const int t   = threadIdx.x;
    const int blk = blockIdx.x;
    const int pix = t >> 1;                  // 0..127
    const int g   = t & 1;                   // group 0/1
    const int P   = blk * TILE + pix;        // global pixel
    const int b   = P >> 12;                 // batch
    const int hw  = P & 4095;

    const float* zp  = z   + (size_t)(b * 18 + g * 9) * HW + hw;
    float*       zqp = out + OFF_ZQ + (size_t)(b * 18 + g * 9) * HW + hw;

    // ---- Phase 1: per-(pixel,group) work ----
    float p[9];
    unsigned gidx = 0;
    float commit = 0.f, ent = 0.f;
#pragma unroll
    for (int j = 0; j < 9; j++) {
        float v = zp[j * HW];
        bool s = v > 0.f;
        gidx = (gidx << 1) | (unsigned)s;
        float zh = s ? 1.f : -1.f;
        zqp[j * HW] = zh;                    // zq forward value == sign(z)
        float d = zh - v;
        commit += d * d;
        // p_j = P(bit=+1) = sigmoid(4 z)
        p[j] = 1.f / (1.f + __expf(-4.f * v));
        // binary entropy via small-side prob q = sigmoid(-4|z|)
        float a = 4.f * fabsf(v);
        float q = 1.f / (1.f + __expf(a));
        ent += -q * __logf(q) - (1.f - q) * log1pf(-q);
    }

    // indices: pair of threads (g=0,g=1) are adjacent lanes
    unsigned other = __shfl_xor_sync(0xffffffffu, gidx, 1);
    out[OFF_GIDX + (size_t)P * 2 + g] = (float)gidx;
    if (g == 0)
        out[OFF_IDX + P] = (float)(gidx * 512u + other);

    // hi/lo product tables: prob[d] = hi[d>>5] * lo[d&31]
    float* sp = sBuf + pix * 96 + g * 48;
    {
        float hi[16];
        hi[0] = 1.f - p[0]; hi[1] = p[0];
#pragma unroll
        for (int c = 1; c < 4; c++) {
            const int n = 1 << c;
#pragma unroll
            for (int i = n - 1; i >= 0; i--) {
                float v = hi[i];
                hi[2 * i + 1] = v * p[c];
                hi[2 * i]     = v * (1.f - p[c]);
            }
        }
#pragma unroll
        for (int i = 0; i < 16; i++) sp[i] = hi[i];
    }
    {
        float lo[32];
        lo[0] = 1.f - p[4]; lo[1] = p[4];
#pragma unroll
        for (int c = 1; c < 5; c++) {
            const int n = 1 << c;
#pragma unroll
            for (int i = n - 1; i >= 0; i--) {
                float v = lo[i];
                lo[2 * i + 1] = v * p[4 + c];
                lo[2 * i]     = v * (1.f - p[4 + c]);
            }
        }
#pragma unroll
        for (int i = 0; i < 32; i++) sp[16 + i] = lo[i];
    }

    // block-reduce commit & entropy (deterministic shuffle tree)
#pragma unroll
    for (int o = 16; o; o >>= 1) {
        commit += __shfl_down_sync(0xffffffffu, commit, o);
        ent    += __shfl_down_sync(0xffffffffu, ent, o);
    }
    const int wid = t >> 5, lid = t & 31;
    if (lid == 0) { sRed[wid] = commit; sRed[8 + wid] = ent; }

    __syncthreads();   // tables ready, sRed ready

    if (t == 0) {
        float c = 0.f, e = 0.f;
#pragma unroll
        for (int w = 0; w < 8; w++) { c += sRed[w]; e += sRed[8 + w]; }
        g_pcommit[blk] = c;
        g_pent[blk]    = e;
    }

    // ---- Phase 2: AVG[i][j] = sum_px hi[px][i]*lo[px][j], a 16x32 (K=128) GEMM
    // per group. 4x4 register tile per thread; 4 pixel-subsets of 32 px each.
    const int tt = t & 63;                 // output tile id
    const int ps = t >> 6;                 // pixel subset 0..3
    const int gg = tt >> 5;                // group
    const int tr = (tt >> 3) & 3;          // hi row-tile (4 rows)
    const int tc = tt & 7;                 // lo col-tile (4 cols)
    float acc[4][4];
#pragma unroll
    for (int r = 0; r < 4; r++)
#pragma unroll
        for (int c = 0; c < 4; c++) acc[r][c] = 0.f;

    const float* tb = sBuf + gg * 48;
#pragma unroll 4
    for (int k = 0; k < 32; k++) {
        const int px = ps * 32 + k;
        const float* bp = tb + px * 96;
        float4 h = *(const float4*)(bp + tr * 4);
        float4 l = *(const float4*)(bp + 16 + tc * 4);
        acc[0][0] += h.x * l.x; acc[0][1] += h.x * l.y; acc[0][2] += h.x * l.z; acc[0][3] += h.x * l.w;
        acc[1][0] += h.y * l.x; acc[1][1] += h.y * l.y; acc[1][2] += h.y * l.z; acc[1][3] += h.y * l.w;
        acc[2][0] += h.z * l.x; acc[2][1] += h.z * l.y; acc[2][2] += h.z * l.z; acc[2][3] += h.z * l.w;
        acc[3][0] += h.w * l.x; acc[3][1] += h.w * l.y; acc[3][2] += h.w * l.z; acc[3][3] += h.w * l.w;
    }

    __syncthreads();   // everyone done reading tables; safe to overwrite

    // stash per-thread 4x4 accs: sBuf[t*16 + r*4 + c]
    float* sa = sBuf + t * 16;
#pragma unroll
    for (int r = 0; r < 4; r++) {
        *(float4*)(sa + r * 4) = make_float4(acc[r][0], acc[r][1], acc[r][2], acc[r][3]);
    }
    __syncthreads();

    // combine 4 pixel-subsets; thread t owns slots 4t..4t+3 (contiguous, same tile row)
    {
        const int slot = 4 * t;
        const int g2   = slot >> 9;
        const int d    = slot & 511;
        const int rr   = d >> 5;
        const int cc   = d & 31;
        const int tt2  = g2 * 32 + (rr >> 2) * 8 + (cc >> 2);
        const int i16  = (rr & 3) * 4;
        float4 s = make_float4(0.f, 0.f, 0.f, 0.f);
#pragma unroll
        for (int q = 0; q < 4; q++) {
            float4 v = *(const float4*)(sBuf + (q * 64 + tt2) * 16 + i16);
            s.x += v.x; s.y += v.y; s.z += v.z; s.w += v.w;
        }
        *(float4*)(g_pavg + (size_t)blk * 1024 + slot) = s;
    }
}

// 512 block-partials -> NSPLIT partials, parallel across 32 blocks
__global__ void __launch_bounds__(256) bsq_reduce() {
    const int slot  = blockIdx.y * 256 + threadIdx.x;
    const int bbase = blockIdx.x * (NBLK / NSPLIT);
    float s = 0.f;
#pragma unroll 8
    for (int j = 0; j < NBLK / NSPLIT; j++)
        s += g_pavg[(size_t)(bbase + j) * 1024 + slot];
    g_red[blockIdx.x * 1024 + slot] = s;
}

__global__ void __launch_bounds__(1024) bsq_final(float* __restrict__ out) {
    __shared__ float sr[64];
    const int t = threadIdx.x;            // one per (g,d) slot
    const int wid = t >> 5, lid = t & 31;

    float s = 0.f;
#pragma unroll
    for (int sp = 0; sp < NSPLIT; sp++) s += g_red[sp * 1024 + t];
    float avg = s * (1.f / (float)NPIX);
    out[OFF_AVGP + t] = avg;

    float cterm = -avg * __logf(avg + 1e-8f);
#pragma unroll
    for (int o = 16; o; o >>= 1) cterm += __shfl_down_sync(0xffffffffu, cterm, o);
    if (lid == 0) sr[wid] = cterm;        // warps 0..31

    // commit / entropy partials: threads 0..511
    float cm = (t < NBLK) ? g_pcommit[t] : 0.f;
    float en = (t < NBLK) ? g_pent[t]    : 0.f;
#pragma unroll
    for (int o = 16; o; o >>= 1) {
        cm += __shfl_down_sync(0xffffffffu, cm, o);
        en += __shfl_down_sync(0xffffffffu, en, o);
    }
    __syncthreads();
    if (lid == 0 && wid < 16) { sr[32 + wid] = cm; sr[48 + wid] = en; }
    __syncthreads();

    if (t == 0) {
        float cbE = 0.f, cmS = 0.f, enS = 0.f;
#pragma unroll
        for (int w = 0; w < 32; w++) cbE += sr[w];
#pragma unroll
        for (int w = 0; w < 16; w++) { cmS += sr[32 + w]; enS += sr[48 + w]; }
        float commit_loss = 0.25f * cmS * (1.f / (float)NPIX);
        float pse = enS * (1.f / (float)NPIX);
        float loss = commit_loss + pse - cbE;    // GAMMA0=GAMMA=ZETA=INV_T=1
        out[OFF_LOSS] = loss;
        out[OFF_CBE]  = cbE;
    }
}

extern "C" void kernel_launch(void* const* d_in, const int* in_sizes, int n_in,
                              void* d_out, int out_size) {
    const float* z = (const float*)d_in[0];
    float* out = (float*)d_out;

    const size_t smem = (TILE * 96 + 64) * sizeof(float);   // 49,408 B
    cudaFuncSetAttribute(bsq_main, cudaFuncAttributeMaxDynamicSharedMemorySize, 64 * 1024);

    bsq_main<<<NBLK, NTHR, smem>>>(z, out);
    bsq_reduce<<<dim3(NSPLIT, 4), 256>>>();
    bsq_final<<<1, 1024>>>(out);
}

// round 3
// speedup vs baseline: 1.6439x; 1.0954x over previous
#include <cuda_runtime.h>
#include <math.h>

// Problem constants
#define NPIX   65536        // B*H*W = 16*64*64
#define HW     4096         // 64*64
#define TILE   128          // pixels per block
#define NBLK   (NPIX/TILE)  // 512
#define NTHR   256
#define NSPLIT 8            // reduction splits (512 blocks -> 8 partials)

// Output layout (flattened tuple, float32):
// zq[16,18,64,64] | loss | cb_entropy | indices[16,64,64] | group_indices[16,64,64,2] | avg_prob[2,512]
#define OFF_ZQ    0
#define OFF_LOSS  1179648
#define OFF_CBE   1179649
#define OFF_IDX   1179650
#define OFF_GIDX  1245186
#define OFF_AVGP  1376258

// Deterministic per-block partials (no float atomics -> bitwise reproducible)
__device__ float g_pavg[NBLK * 1024];
__device__ float g_red[NSPLIT * 1024];
__device__ float g_pcommit[NBLK];
__device__ float g_pent[NBLK];

__global__ void __launch_bounds__(NTHR) bsq_main(const float* __restrict__ z,
                                                 float* __restrict__ out) {
    extern __shared__ float sBuf[];          // TILE*96 table floats + 64 reduction
    float* sRed = sBuf + TILE * 96;

    const int t   = threadIdx.x;
    const int blk = blockIdx.x;
    const int pix = t >> 1;                  // 0..127
    const int g   = t & 1;                   // group 0/1
    const int P   = blk * TILE + pix;        // global pixel
    const int b   = P >> 12;                 // batch
    const int hw  = P & 4095;

    const float* zp  = z   + (size_t)(b * 18 + g * 9) * HW + hw;
    float*       zqp = out + OFF_ZQ + (size_t)(b * 18 + g * 9) * HW + hw;

    // ---- Phase 1: per-(pixel,group) work ----
    // Binary-entropy factorization with a single log:
    //   H(sigmoid(a)) = ln(1+e^{-a}) + a * sigmoid(-a),  a = 4|v| >= 0
    //   ent = ln( prod_j (1+E_j) ) + sum_j q_j * a_j,   E_j = e^{-a_j}, q_j = E_j/(1+E_j)
    float p[9];
    unsigned gidx = 0;
    float commit = 0.f, qa = 0.f, prodE = 1.f;
#pragma unroll
    for (int j = 0; j < 9; j++) {
        float v = zp[j * HW];
        bool s = v > 0.f;
        gidx = (gidx << 1) | (unsigned)s;
        float zh = s ? 1.f : -1.f;
        zqp[j * HW] = zh;                    // zq forward value == sign(z)
        float d = zh - v;
        commit += d * d;
        float a = 4.f * fabsf(v);
        float E = __expf(-a);
        float onepE = 1.f + E;
        float r = __fdividef(1.f, onepE);    // MUFU.RCP-based, ~1ulp
        float q = E * r;                     // small-side prob
        p[j] = s ? r : q;                    // sigmoid(4v)
        qa += q * a;
        prodE *= onepE;
    }
    float ent = __logf(prodE) + qa;

    // indices: pair of threads (g=0,g=1) are adjacent lanes
    unsigned other = __shfl_xor_sync(0xffffffffu, gidx, 1);
    out[OFF_GIDX + (size_t)P * 2 + g] = (float)gidx;
    if (g == 0)
        out[OFF_IDX + P] = (float)(gidx * 512u + other);

    // hi/lo product tables: prob[d] = hi[d>>5] * lo[d&31]
    float* sp = sBuf + pix * 96 + g * 48;
    {
        float hi[16];
        hi[0] = 1.f - p[0]; hi[1] = p[0];
#pragma unroll
        for (int c = 1; c < 4; c++) {
            const int n = 1 << c;
#pragma unroll
            for (int i = n - 1; i >= 0; i--) {
                float v = hi[i];
                hi[2 * i + 1] = v * p[c];
                hi[2 * i]     = v * (1.f - p[c]);
            }
        }
#pragma unroll
        for (int i = 0; i < 16; i++) sp[i] = hi[i];
    }
    {
        float lo[32];
        lo[0] = 1.f - p[4]; lo[1] = p[4];
#pragma unroll
        for (int c = 1; c < 5; c++) {
            const int n = 1 << c;
#pragma unroll
            for (int i = n - 1; i >= 0; i--) {
                float v = lo[i];
                lo[2 * i + 1] = v * p[4 + c];
                lo[2 * i]     = v * (1.f - p[4 + c]);
            }
        }
#pragma unroll
        for (int i = 0; i < 32; i++) sp[16 + i] = lo[i];
    }

    // block-reduce commit & entropy (deterministic shuffle tree)
#pragma unroll
    for (int o = 16; o; o >>= 1) {
        commit += __shfl_down_sync(0xffffffffu, commit, o);
        ent    += __shfl_down_sync(0xffffffffu, ent, o);
    }
    const int wid = t >> 5, lid = t & 31;
    if (lid == 0) { sRed[wid] = commit; sRed[8 + wid] = ent; }

    __syncthreads();   // tables ready, sRed ready

    if (t == 0) {
        float c = 0.f, e = 0.f;
#pragma unroll
        for (int w = 0; w < 8; w++) { c += sRed[w]; e += sRed[8 + w]; }
        g_pcommit[blk] = c;
        g_pent[blk]    = e;
    }

    // ---- Phase 2: AVG[i][j] = sum_px hi[px][i]*lo[px][j], a 16x32 (K=128) GEMM
    // per group. 4x4 register tile per thread; 4 pixel-subsets of 32 px each.
    const int tt = t & 63;                 // output tile id
    const int ps = t >> 6;                 // pixel subset 0..3
    const int gg = tt >> 5;                // group
    const int tr = (tt >> 3) & 3;          // hi row-tile (4 rows)
    const int tc = tt & 7;                 // lo col-tile (4 cols)
    float acc[4][4];
#pragma unroll
    for (int r = 0; r < 4; r++)
#pragma unroll
        for (int c = 0; c < 4; c++) acc[r][c] = 0.f;

    const float* tb = sBuf + gg * 48;
#pragma unroll 4
    for (int k = 0; k < 32; k++) {
        const int px = ps * 32 + k;
        const float* bp = tb + px * 96;
        float4 h = *(const float4*)(bp + tr * 4);
        float4 l = *(const float4*)(bp + 16 + tc * 4);
        acc[0][0] += h.x * l.x; acc[0][1] += h.x * l.y; acc[0][2] += h.x * l.z; acc[0][3] += h.x * l.w;
        acc[1][0] += h.y * l.x; acc[1][1] += h.y * l.y; acc[1][2] += h.y * l.z; acc[1][3] += h.y * l.w;
        acc[2][0] += h.z * l.x; acc[2][1] += h.z * l.y; acc[2][2] += h.z * l.z; acc[2][3] += h.z * l.w;
        acc[3][0] += h.w * l.x; acc[3][1] += h.w * l.y; acc[3][2] += h.w * l.z; acc[3][3] += h.w * l.w;
    }

    __syncthreads();   // everyone done reading tables; safe to overwrite

    // stash per-thread 4x4 accs: sBuf[t*16 + r*4 + c]
    float* sa = sBuf + t * 16;
#pragma unroll
    for (int r = 0; r < 4; r++) {
        *(float4*)(sa + r * 4) = make_float4(acc[r][0], acc[r][1], acc[r][2], acc[r][3]);
    }
    __syncthreads();

    // combine 4 pixel-subsets; thread t owns slots 4t..4t+3 (contiguous, same tile row)
    {
        const int slot = 4 * t;
        const int g2   = slot >> 9;
        const int d    = slot & 511;
        const int rr   = d >> 5;
        const int cc   = d & 31;
        const int tt2  = g2 * 32 + (rr >> 2) * 8 + (cc >> 2);
        const int i16  = (rr & 3) * 4;
        float4 s = make_float4(0.f, 0.f, 0.f, 0.f);
#pragma unroll
        for (int q = 0; q < 4; q++) {
            float4 v = *(const float4*)(sBuf + (q * 64 + tt2) * 16 + i16);
            s.x += v.x; s.y += v.y; s.z += v.z; s.w += v.w;
        }
        *(float4*)(g_pavg + (size_t)blk * 1024 + slot) = s;
    }
}

// 512 block-partials -> NSPLIT partials, parallel across 32 blocks
__global__ void __launch_bounds__(256) bsq_reduce() {
    const int slot  = blockIdx.y * 256 + threadIdx.x;
    const int bbase = blockIdx.x * (NBLK / NSPLIT);
    float s = 0.f;
#pragma unroll 8
    for (int j = 0; j < NBLK / NSPLIT; j++)
        s += g_pavg[(size_t)(bbase + j) * 1024 + slot];
    g_red[blockIdx.x * 1024 + slot] = s;
}

__global__ void __launch_bounds__(1024) bsq_final(float* __restrict__ out) {
    __shared__ float sr[64];
    const int t = threadIdx.x;            // one per (g,d) slot
    const int wid = t >> 5, lid = t & 31;

    float s = 0.f;
#pragma unroll
    for (int sp = 0; sp < NSPLIT; sp++) s += g_red[sp * 1024 + t];
    float avg = s * (1.f / (float)NPIX);
    out[OFF_AVGP + t] = avg;

    float cterm = -avg * __logf(avg + 1e-8f);
#pragma unroll
    for (int o = 16; o; o >>= 1) cterm += __shfl_down_sync(0xffffffffu, cterm, o);
    if (lid == 0) sr[wid] = cterm;        // warps 0..31

    // commit / entropy partials: threads 0..511
    float cm = (t < NBLK) ? g_pcommit[t] : 0.f;
    float en = (t < NBLK) ? g_pent[t]    : 0.f;
#pragma unroll
    for (int o = 16; o; o >>= 1) {
        cm += __shfl_down_sync(0xffffffffu, cm, o);
        en += __shfl_down_sync(0xffffffffu, en, o);
    }
    __syncthreads();
    if (lid == 0 && wid < 16) { sr[32 + wid] = cm; sr[48 + wid] = en; }
    __syncthreads();

    if (t == 0) {
        float cbE = 0.f, cmS = 0.f, enS = 0.f;
#pragma unroll
        for (int w = 0; w < 32; w++) cbE += sr[w];
#pragma unroll
        for (int w = 0; w < 16; w++) { cmS += sr[32 + w]; enS += sr[48 + w]; }
        float commit_loss = 0.25f * cmS * (1.f / (float)NPIX);
        float pse = enS * (1.f / (float)NPIX);
        float loss = commit_loss + pse - cbE;    // GAMMA0=GAMMA=ZETA=INV_T=1
        out[OFF_LOSS] = loss;
        out[OFF_CBE]  = cbE;
    }
}

extern "C" void kernel_launch(void* const* d_in, const int* in_sizes, int n_in,
                              void* d_out, int out_size) {
    const float* z = (const float*)d_in[0];
    float* out = (float*)d_out;

    const size_t smem = (TILE * 96 + 64) * sizeof(float);   // 49,408 B
    cudaFuncSetAttribute(bsq_main, cudaFuncAttributeMaxDynamicSharedMemorySize, 64 * 1024);

    bsq_main<<<NBLK, NTHR, smem>>>(z, out);
    bsq_reduce<<<dim3(NSPLIT, 4), 256>>>();
    bsq_final<<<1, 1024>>>(out);
}

// round 5
// speedup vs baseline: 1.7645x; 1.0734x over previous
#include <cuda_runtime.h>
#include <math.h>

// Problem constants
#define NPIX   65536        // B*H*W = 16*64*64
#define HW     4096         // 64*64
#define TILE   128          // pixels per block
#define NBLK   (NPIX/TILE)  // 512
#define NTHR   256
#define NSPLIT 8            // reduction splits (512 blocks -> 8 partials)

// Transposed table layout: sT[row*RS + g*GOFF + pix]
//   rows 0..15  = hi[i],  rows 16..47 = lo[j]
//   RS = 292 (RS/4 = 73 odd -> rows spread over bank-groups; 16B aligned)
//   GOFF = 144 (mod 32 == 16 -> phase-1 STS conflict-free)
#define RS    292
#define GOFF  144
#define SRED_OFF (48 * RS)       // 14016
#define SMEM_FLOATS (SRED_OFF + 64)

// Output layout (flattened tuple, float32):
// zq[16,18,64,64] | loss | cb_entropy | indices[16,64,64] | group_indices[16,64,64,2] | avg_prob[2,512]
#define OFF_ZQ    0
#define OFF_LOSS  1179648
#define OFF_CBE   1179649
#define OFF_IDX   1179650
#define OFF_GIDX  1245186
#define OFF_AVGP  1376258

// Deterministic per-block partials (no float atomics -> bitwise reproducible)
__device__ float g_pavg[NBLK * 1024];
__device__ float g_red[NSPLIT * 1024];
__device__ float g_pcommit[NBLK];
__device__ float g_pent[NBLK];

__device__ __forceinline__ void fma2(unsigned long long& acc,
                                     unsigned long long a, unsigned long long b) {
    asm("fma.rn.f32x2 %0, %1, %2, %0;" : "+l"(acc) : "l"(a), "l"(b));
}
__device__ __forceinline__ float hsum2(unsigned long long acc) {
    float lo, hi;
    asm("mov.b64 {%0, %1}, %2;" : "=f"(lo), "=f"(hi) : "l"(acc));
    return lo + hi;
}

__global__ void __launch_bounds__(NTHR) bsq_main(const float* __restrict__ z,
                                                 float* __restrict__ out) {
    extern __shared__ float sT[];
    float* sRed = sT + SRED_OFF;

    const int t   = threadIdx.x;
    const int blk = blockIdx.x;
    const int pix = t >> 1;                  // 0..127
    const int g   = t & 1;                   // group 0/1
    const int P   = blk * TILE + pix;        // global pixel
    const int b   = P >> 12;                 // batch
    const int hw  = P & 4095;

    const float* zp  = z   + (size_t)(b * 18 + g * 9) * HW + hw;
    float*       zqp = out + OFF_ZQ + (size_t)(b * 18 + g * 9) * HW + hw;

    // ---- Phase 1: per-(pixel,group) work ----
    // ent = ln( prod_j (1+E_j) ) + sum_j q_j*a_j,  E=e^{-4|v|}, q=E/(1+E)
    float p[9];
    unsigned gidx = 0;
    float commit = 0.f, qa = 0.f, prodE = 1.f;
#pragma unroll
    for (int j = 0; j < 9; j++) {
        float v = zp[j * HW];
        bool s = v > 0.f;
        gidx = (gidx << 1) | (unsigned)s;
        float zh = s ? 1.f : -1.f;
        zqp[j * HW] = zh;                    // zq forward value == sign(z)
        float d = zh - v;
        commit += d * d;
        float a = 4.f * fabsf(v);
        float E = __expf(-a);
        float onepE = 1.f + E;
        float r = __fdividef(1.f, onepE);
        float q = E * r;
        p[j] = s ? r : q;                    // sigmoid(4v)
        qa += q * a;
        prodE *= onepE;
    }
    float ent = __logf(prodE) + qa;

    // indices: pair of threads (g=0,g=1) are adjacent lanes
    unsigned other = __shfl_xor_sync(0xffffffffu, gidx, 1);
    out[OFF_GIDX + (size_t)P * 2 + g] = (float)gidx;
    if (g == 0)
        out[OFF_IDX + P] = (float)(gidx * 512u + other);

    // build hi[16]/lo[32] in regs, write transposed (conflict-free STS)
    const int col = g * GOFF + pix;
    {
        float hi[16];
        hi[0] = 1.f - p[0]; hi[1] = p[0];
#pragma unroll
        for (int c = 1; c < 4; c++) {
            const int n = 1 << c;
#pragma unroll
            for (int i = n - 1; i >= 0; i--) {
                float v = hi[i];
                hi[2 * i + 1] = v * p[c];
                hi[2 * i]     = v * (1.f - p[c]);
            }
        }
#pragma unroll
        for (int i = 0; i < 16; i++) sT[i * RS + col] = hi[i];
    }
    {
        float lo[32];
        lo[0] = 1.f - p[4]; lo[1] = p[4];
#pragma unroll
        for (int c = 1; c < 5; c++) {
            const int n = 1 << c;
#pragma unroll
            for (int i = n - 1; i >= 0; i--) {
                float v = lo[i];
                lo[2 * i + 1] = v * p[4 + c];
                lo[2 * i]     = v * (1.f - p[4 + c]);
            }
        }
#pragma unroll
        for (int i = 0; i < 32; i++) sT[(16 + i) * RS + col] = lo[i];
    }

    // block-reduce commit & entropy (deterministic shuffle tree)
#pragma unroll
    for (int o = 16; o; o >>= 1) {
        commit += __shfl_down_sync(0xffffffffu, commit, o);
        ent    += __shfl_down_sync(0xffffffffu, ent, o);
    }
    const int wid = t >> 5, lid = t & 31;
    if (lid == 0) { sRed[wid] = commit; sRed[8 + wid] = ent; }

    __syncthreads();   // tables + sRed ready

    if (t == 0) {
        float c = 0.f, e = 0.f;
#pragma unroll
        for (int w = 0; w < 8; w++) { c += sRed[w]; e += sRed[8 + w]; }
        g_pcommit[blk] = c;
        g_pent[blk]    = e;
    }

    // ---- Phase 2: AVG[g][i][j] = sum_px hi[g][px][i]*lo[g][px][j]
    // 2x2 strided tile per thread: i in {ti, ti+8}, j in {tj, tj+16}.
    // Full 128-px sweep, LDS.128 along px, packed fma.rn.f32x2.
    {
        const int gg  = t >> 7;
        const int rem = t & 127;
        const int ti  = rem >> 4;            // 0..7
        const int tj  = rem & 15;            // 0..15
        const float* pA = sT + (ti)      * RS + gg * GOFF;
        const float* pB = sT + (ti + 8)  * RS + gg * GOFF;
        const float* pC = sT + (16 + tj) * RS + gg * GOFF;
        const float* pD = sT + (32 + tj) * RS + gg * GOFF;

        unsigned long long aa = 0ull, ab = 0ull, ba = 0ull, bb = 0ull;
#pragma unroll 4
        for (int px = 0; px < TILE; px += 4) {
            ulonglong2 hA = *(const ulonglong2*)(pA + px);
            ulonglong2 hB = *(const ulonglong2*)(pB + px);
            ulonglong2 lA = *(const ulonglong2*)(pC + px);
            ulonglong2 lB = *(const ulonglong2*)(pD + px);
            fma2(aa, hA.x, lA.x); fma2(aa, hA.y, lA.y);
            fma2(ab, hA.x, lB.x); fma2(ab, hA.y, lB.y);
            fma2(ba, hB.x, lA.x); fma2(ba, hB.y, lA.y);
            fma2(bb, hB.x, lB.x); fma2(bb, hB.y, lB.y);
        }

        float* gp = g_pavg + (size_t)blk * 1024 + gg * 512;
        gp[(ti)     * 32 + tj]      = hsum2(aa);
        gp[(ti)     * 32 + tj + 16] = hsum2(ab);
        gp[(ti + 8) * 32 + tj]      = hsum2(ba);
        gp[(ti + 8) * 32 + tj + 16] = hsum2(bb);
    }
}

// 512 block-partials -> NSPLIT partials, parallel across 32 blocks
__global__ void __launch_bounds__(256) bsq_reduce() {
    const int slot  = blockIdx.y * 256 + threadIdx.x;
    const int bbase = blockIdx.x * (NBLK / NSPLIT);
    float s = 0.f;
#pragma unroll 8
    for (int j = 0; j < NBLK / NSPLIT; j++)
        s += g_pavg[(size_t)(bbase + j) * 1024 + slot];
    g_red[blockIdx.x * 1024 + slot] = s;
}

__global__ void __launch_bounds__(1024) bsq_final(float* __restrict__ out) {
    __shared__ float sr[64];
    const int t = threadIdx.x;            // one per (g,d) slot
    const int wid = t >> 5, lid = t & 31;

    float s = 0.f;
#pragma unroll
    for (int sp = 0; sp < NSPLIT; sp++) s += g_red[sp * 1024 + t];
    float avg = s * (1.f / (float)NPIX);
    out[OFF_AVGP + t] = avg;

    float cterm = -avg * __logf(avg + 1e-8f);
#pragma unroll
    for (int o = 16; o; o >>= 1) cterm += __shfl_down_sync(0xffffffffu, cterm, o);
    if (lid == 0) sr[wid] = cterm;        // warps 0..31

    // commit / entropy partials: threads 0..511
    float cm = (t < NBLK) ? g_pcommit[t] : 0.f;
    float en = (t < NBLK) ? g_pent[t]    : 0.f;
#pragma unroll
    for (int o = 16; o; o >>= 1) {
        cm += __shfl_down_sync(0xffffffffu, cm, o);
        en += __shfl_down_sync(0xffffffffu, en, o);
    }
    __syncthreads();
    if (lid == 0 && wid < 16) { sr[32 + wid] = cm; sr[48 + wid] = en; }
    __syncthreads();

    if (t == 0) {
        float cbE = 0.f, cmS = 0.f, enS = 0.f;
#pragma unroll
        for (int w = 0; w < 32; w++) cbE += sr[w];
#pragma unroll
        for (int w = 0; w < 16; w++) { cmS += sr[32 + w]; enS += sr[48 + w]; }
        float commit_loss = 0.25f * cmS * (1.f / (float)NPIX);
        float pse = enS * (1.f / (float)NPIX);
        float loss = commit_loss + pse - cbE;    // GAMMA0=GAMMA=ZETA=INV_T=1
        out[OFF_LOSS] = loss;
        out[OFF_CBE]  = cbE;
    }
}

extern "C" void kernel_launch(void* const* d_in, const int* in_sizes, int n_in,
                              void* d_out, int out_size) {
    const float* z = (const float*)d_in[0];
    float* out = (float*)d_out;

    const size_t smem = SMEM_FLOATS * sizeof(float);   // 56,320 B
    cudaFuncSetAttribute(bsq_main, cudaFuncAttributeMaxDynamicSharedMemorySize, 64 * 1024);

    bsq_main<<<NBLK, NTHR, smem>>>(z, out);
    bsq_reduce<<<dim3(NSPLIT, 4), 256>>>();
    bsq_final<<<1, 1024>>>(out);
}